// round 16
// baseline (speedup 1.0000x reference)
#include <cuda_runtime.h>
#include <cuda_fp16.h>
#include <cstdint>
#include <limits.h>

#define N_NODES 50000
#define N_EDGES 800000
#define IN_DIM  256
#define HID     128
#define LEAKY   0.01f
#define SCAN_BLK 196                       // ceil(50000 / 256)

// ---------------- scratch (device globals; device-side use ONLY) -------------
// Relies on zero-init of __device__ globals at module load for the FIRST run;
// scanAB/scanC restore the zero-state for graph replays.
__device__ __align__(16) __half2 g_zh[N_NODES * 64];        // z fp16 (gather payload)
__device__ __align__(16) __half2 g_hh2[N_NODES * IN_DIM/2]; // input h in fp16
__device__ __align__(16) __half2 g_h1h2[N_NODES * HID/2];   // layer-1 out in fp16
__device__ __align__(16) __half  g_W1h[HID * IN_DIM];       // fp16 W1
__device__ __align__(16) __half  g_W2h[HID * HID];          // fp16 W2
__device__ float g_ssrc[N_NODES];
__device__ float g_sdst[N_NODES];
__device__ int   g_cnt[N_NODES];           // zero at entry of every run
__device__ int   g_off[N_NODES + 1];
__device__ int   g_cur[N_NODES];
__device__ int   g_esrc[N_EDGES];          // CSR (by dst) -> src node id
__device__ int   g_bsum[SCAN_BLK];
__device__ int   g_boff[SCAN_BLK];
__device__ int   g_done;                   // scanAB last-block counter

// ---------------- small helpers ----------------------------------------------
__device__ __forceinline__ uint32_t smem_u32(const void* p) {
    uint32_t a;
    asm("{ .reg .u64 t; cvta.to.shared.u64 t, %1; cvt.u32.u64 %0, t; }" : "=r"(a) : "l"(p));
    return a;
}
__device__ __forceinline__ void cp16z(uint32_t dst, const void* src, bool valid) {
    int sz = valid ? 16 : 0;
    asm volatile("cp.async.cg.shared.global [%0], [%1], 16, %2;"
                 :: "r"(dst), "l"(src), "r"(sz));
}
__device__ __forceinline__ void cp16(uint32_t dst, const void* src) {
    asm volatile("cp.async.cg.shared.global [%0], [%1], 16;" :: "r"(dst), "l"(src));
}
#define CP_COMMIT() asm volatile("cp.async.commit_group;" ::: "memory")
#define CP_WAIT(N)  asm volatile("cp.async.wait_group %0;" :: "n"(N) : "memory")

__device__ __forceinline__ void mma_f16(float* c, const uint32_t* a, const uint32_t* b) {
    asm volatile(
        "mma.sync.aligned.m16n8k16.row.col.f32.f16.f16.f32 "
        "{%0,%1,%2,%3}, {%4,%5,%6,%7}, {%8,%9}, {%0,%1,%2,%3};"
        : "+f"(c[0]), "+f"(c[1]), "+f"(c[2]), "+f"(c[3])
        : "r"(a[0]), "r"(a[1]), "r"(a[2]), "r"(a[3]), "r"(b[0]), "r"(b[1]));
}

// ---------------- CSR build --------------------------------------------------
__global__ void hist_kernel(const int* __restrict__ dst) {
    int i = blockIdx.x * blockDim.x + threadIdx.x;
    if (i * 4 < N_EDGES) {
        int4 d = ((const int4*)dst)[i];
        atomicAdd(&g_cnt[d.x], 1);
        atomicAdd(&g_cnt[d.y], 1);
        atomicAdd(&g_cnt[d.z], 1);
        atomicAdd(&g_cnt[d.w], 1);
    }
}
// scanA + scanB fused: per-block sums; LAST finishing block scans the sums.
__global__ __launch_bounds__(256) void scanAB_kernel() {
    __shared__ int sm[256];
    __shared__ int isLast;
    int t = threadIdx.x, i = blockIdx.x * 256 + t;
    int c = (i < N_NODES) ? g_cnt[i] : 0;
    sm[t] = c;
    __syncthreads();
    for (int o = 128; o > 0; o >>= 1) {
        if (t < o) sm[t] += sm[t + o];
        __syncthreads();
    }
    if (t == 0) {
        g_bsum[blockIdx.x] = sm[0];
        __threadfence();
        int prev = atomicAdd(&g_done, 1);
        isLast = (prev == SCAN_BLK - 1) ? 1 : 0;
    }
    __syncthreads();
    if (isLast) {
        int v = (t < SCAN_BLK) ? g_bsum[t] : 0;
        sm[t] = v;
        __syncthreads();
        for (int o = 1; o < 256; o <<= 1) {
            int add = (t >= o) ? sm[t - o] : 0;
            __syncthreads();
            sm[t] += add;
            __syncthreads();
        }
        if (t < SCAN_BLK) g_boff[t] = sm[t] - v;
        if (t == 0) {
            g_off[N_NODES] = N_EDGES;
            g_done = 0;                    // reset for next run
        }
    }
}
// local scan + offsets; re-zeroes g_cnt for the next run.
__global__ __launch_bounds__(256) void scanC_kernel() {
    __shared__ int sm[256];
    int t = threadIdx.x, i = blockIdx.x * 256 + t;
    int c = (i < N_NODES) ? g_cnt[i] : 0;
    sm[t] = c;
    __syncthreads();
    for (int o = 1; o < 256; o <<= 1) {
        int add = (t >= o) ? sm[t - o] : 0;
        __syncthreads();
        sm[t] += add;
        __syncthreads();
    }
    if (i < N_NODES) {
        int prefix = g_boff[blockIdx.x] + sm[t] - c;  // exclusive
        g_off[i] = prefix;
        g_cur[i] = prefix;
        g_cnt[i] = 0;
    }
}
__global__ void fill_kernel(const int* __restrict__ dst,
                            const int* __restrict__ src) {
    int i = blockIdx.x * blockDim.x + threadIdx.x;
    if (i * 4 < N_EDGES) {
        int4 d = ((const int4*)dst)[i];
        int4 s = ((const int4*)src)[i];
        int p0 = atomicAdd(&g_cur[d.x], 1);
        int p1 = atomicAdd(&g_cur[d.y], 1);
        int p2 = atomicAdd(&g_cur[d.z], 1);
        int p3 = atomicAdd(&g_cur[d.w], 1);
        g_esrc[p0] = s.x;
        g_esrc[p1] = s.y;
        g_esrc[p2] = s.z;
        g_esrc[p3] = s.w;
    }
}

// ---------------- precision conversions (W + h, fused) -----------------------
__global__ void conv_kernel(const float* __restrict__ W1,
                            const float* __restrict__ W2,
                            const float* __restrict__ h) {
    int i = blockIdx.x * blockDim.x + threadIdx.x;
    if (i < HID * IN_DIM) g_W1h[i] = __float2half_rn(W1[i]);
    if (i < HID * HID)    g_W2h[i] = __float2half_rn(W2[i]);
    if (i * 8 < N_NODES * IN_DIM) {
        float4 v0 = ((const float4*)h)[i * 2];
        float4 v1 = ((const float4*)h)[i * 2 + 1];
        __half2 o0 = __float22half2_rn(make_float2(v0.x, v0.y));
        __half2 o1 = __float22half2_rn(make_float2(v0.z, v0.w));
        __half2 o2 = __float22half2_rn(make_float2(v1.x, v1.y));
        __half2 o3 = __float22half2_rn(make_float2(v1.z, v1.w));
        uint4 pk;
        pk.x = *(uint32_t*)&o0; pk.y = *(uint32_t*)&o1;
        pk.z = *(uint32_t*)&o2; pk.w = *(uint32_t*)&o3;
        ((uint4*)g_hh2)[i] = pk;
    }
}

// ---------------- cp.async 3-stage pipelined fp16 GEMM -----------------------
// z(fp16) = A @ W^T + bias; fused attention dots -> g_ssrc / g_sdst.
// BM=128, BN=128, BK=32; 256 threads = 8 warps; warp tile 32x64.
// 3 stages, prefetch distance 2 -> full DRAM latency coverage per BK tile.
#define STAGE_BYTES 20480
#define NSTAGE 3
#define GEMM_SMEM   (NSTAGE * STAGE_BYTES + 1024)

template <int K, bool L1>
__global__ __launch_bounds__(256) void gemm_mma(
    const float* __restrict__ bias, const float* __restrict__ avec)
{
    const __half* __restrict__ A  = L1 ? (const __half*)g_hh2 : (const __half*)g_h1h2;
    const __half* __restrict__ Wh = L1 ? g_W1h : g_W2h;

    extern __shared__ __align__(16) char dsm[];
    float* sSS = (float*)(dsm + NSTAGE * STAGE_BYTES);
    float* sSD = sSS + 128;
    uint32_t smBase = smem_u32(dsm);

    int tid  = threadIdx.x;
    int wid  = tid >> 5, lane = tid & 31;
    int wr   = wid & 3;
    int wc   = wid >> 2;
    int g4   = lane >> 2;
    int q4   = lane & 3;
    int m0   = blockIdx.x * 128;

    float acc[2][8][4];
#pragma unroll
    for (int mt = 0; mt < 2; ++mt)
#pragma unroll
        for (int nt = 0; nt < 8; ++nt)
#pragma unroll
            for (int j = 0; j < 4; ++j) acc[mt][nt][j] = 0.f;

    const int NT = K / 32;

    auto load_tile = [&](int t, int stage) {
        int k0 = t * 32;
#pragma unroll
        for (int x = tid; x < 1024; x += 256) {
            if (x < 512) {
                int row = x >> 2, q = x & 3;
                int gr = m0 + row;
                uint32_t d = smBase + stage * STAGE_BYTES + row * 80 + q * 16;
                cp16z(d, A + (size_t)gr * K + k0 + q * 8, gr < N_NODES);
            } else {
                int y = x - 512;
                int row = y >> 2, q = y & 3;
                uint32_t d = smBase + stage * STAGE_BYTES + 10240 + row * 80 + q * 16;
                cp16(d, Wh + (size_t)row * K + k0 + q * 8);
            }
        }
        CP_COMMIT();
    };

    // prologue: prefetch stages 0 and 1
    load_tile(0, 0);
    if (NT > 1) load_tile(1, 1);
    for (int t = 0; t < NT; ++t) {
        int cur = t % NSTAGE;
        // wait until stage t is resident (keep at most 1 younger group pending)
        if (t + 2 < NT) { CP_WAIT(1); }
        else if (t + 1 < NT) { CP_WAIT(1); }
        else { CP_WAIT(0); }
        __syncthreads();

        const uint32_t* Ab = (const uint32_t*)(dsm + cur * STAGE_BYTES);
        const uint32_t* Wb = (const uint32_t*)(dsm + cur * STAGE_BYTES + 10240);
#pragma unroll
        for (int c = 0; c < 2; ++c) {
            int co = c * 8;
            uint32_t afr[2][4];
#pragma unroll
            for (int mt = 0; mt < 2; ++mt) {
                int rb = wr * 32 + mt * 16;
                afr[mt][0] = Ab[(rb + g4) * 20 + co + q4];
                afr[mt][1] = Ab[(rb + 8 + g4) * 20 + co + q4];
                afr[mt][2] = Ab[(rb + g4) * 20 + co + 4 + q4];
                afr[mt][3] = Ab[(rb + 8 + g4) * 20 + co + 4 + q4];
            }
#pragma unroll
            for (int nt = 0; nt < 8; ++nt) {
                int cb = wc * 64 + nt * 8;
                uint32_t bfr[2];
                bfr[0] = Wb[(cb + g4) * 20 + co + q4];
                bfr[1] = Wb[(cb + g4) * 20 + co + 4 + q4];
#pragma unroll
                for (int mt = 0; mt < 2; ++mt)
                    mma_f16(acc[mt][nt], afr[mt], bfr);
            }
        }
        __syncthreads();     // stage `cur` free for reuse
        if (t + 2 < NT) load_tile(t + 2, (t + 2) % NSTAGE);
    }

    if (tid < 128) { sSS[tid] = 0.f; sSD[tid] = 0.f; }
    __syncthreads();

    // epilogue: + bias, store z (fp16), accumulate attention dots (fp32)
#pragma unroll
    for (int mt = 0; mt < 2; ++mt) {
        float ss0 = 0.f, sd0 = 0.f, ss1 = 0.f, sd1 = 0.f;
        int r0 = m0 + wr * 32 + mt * 16 + g4;
        int r1 = r0 + 8;
#pragma unroll
        for (int nt = 0; nt < 8; ++nt) {
            int cb = wc * 64 + nt * 8 + q4 * 2;
            float bx = __ldg(&bias[cb]), by = __ldg(&bias[cb + 1]);
            float asx = __ldg(&avec[cb]),       asy = __ldg(&avec[cb + 1]);
            float adx = __ldg(&avec[128 + cb]), ady = __ldg(&avec[128 + cb + 1]);
            float v0 = acc[mt][nt][0] + bx, v1 = acc[mt][nt][1] + by;
            float v2 = acc[mt][nt][2] + bx, v3 = acc[mt][nt][3] + by;
            ss0 += v0 * asx + v1 * asy;
            sd0 += v0 * adx + v1 * ady;
            ss1 += v2 * asx + v3 * asy;
            sd1 += v2 * adx + v3 * ady;
            if (r0 < N_NODES)
                g_zh[(size_t)r0 * 64 + (cb >> 1)] = __float22half2_rn(make_float2(v0, v1));
            if (r1 < N_NODES)
                g_zh[(size_t)r1 * 64 + (cb >> 1)] = __float22half2_rn(make_float2(v2, v3));
        }
        int lr0 = wr * 32 + mt * 16 + g4;
        atomicAdd(&sSS[lr0], ss0);
        atomicAdd(&sSD[lr0], sd0);
        atomicAdd(&sSS[lr0 + 8], ss1);
        atomicAdd(&sSD[lr0 + 8], sd1);
    }
    __syncthreads();
    if (tid < 128 && m0 + tid < N_NODES) {
        g_ssrc[m0 + tid] = sSS[tid];
        g_sdst[m0 + tid] = sSD[tid];
    }
}

// ---------------- fused softmax + weighted aggregation + ELU ----------------
// Two nodes per warp (16 lanes each, uint4 row gathers). Single-pass exp+sum.
template <bool ToExt>
__global__ __launch_bounds__(256) void agg_kernel(const float* __restrict__ ab_ptr,
                                                  float* __restrict__ out_ext)
{
    __shared__ float sWgt[16][64];
    __shared__ int   sSrc[16][64];
    int gt    = blockIdx.x * blockDim.x + threadIdx.x;
    int node  = gt >> 4;                    // half-warp per node
    int lane  = gt & 15;                    // 0..15
    int hw    = (threadIdx.x >> 4);         // 0..15 half-warp slot
    if (node >= N_NODES) return;
    int beg = g_off[node], end = g_off[node + 1], deg = end - beg;
    float sdn = g_sdst[node] + ab_ptr[0];

    float ex[4]; int snv[4];
    float S = 0.f;
#pragma unroll
    for (int l = 0; l < 4; ++l) {
        int s = beg + lane + l * 16;
        float x = 0.f; int sn = 0;
        if (s < end) {
            sn = g_esrc[s];
            float e = g_ssrc[sn] + sdn;
            e = (e > 0.f) ? e : LEAKY * e;
            x = __expf(e);
        }
        ex[l] = x; snv[l] = sn;
        S += x;
    }
    for (int s = beg + 64 + lane; s < end; s += 16) {
        float e = g_ssrc[g_esrc[s]] + sdn;
        e = (e > 0.f) ? e : LEAKY * e;
        S += __expf(e);
    }
#pragma unroll
    for (int o = 8; o > 0; o >>= 1) S += __shfl_xor_sync(0xffffffffu, S, o);
    float inv = (deg > 0) ? (1.f / S) : 0.f;

#pragma unroll
    for (int l = 0; l < 4; ++l) {
        int idx = lane + l * 16;
        if (beg + idx < end) {
            sWgt[hw][idx] = ex[l] * inv;
            sSrc[hw][idx] = snv[l];
        }
    }
    __syncwarp();

    float acc[8] = {0.f, 0.f, 0.f, 0.f, 0.f, 0.f, 0.f, 0.f};
    int nin = deg < 64 ? deg : 64;
#pragma unroll 8
    for (int i = 0; i < nin; ++i) {
        float w  = sWgt[hw][i];
        int   sn = sSrc[hw][i];
        uint4 zr = ((const uint4*)g_zh)[(size_t)sn * 16 + lane];
        float2 f0 = __half22float2(*reinterpret_cast<__half2*>(&zr.x));
        float2 f1 = __half22float2(*reinterpret_cast<__half2*>(&zr.y));
        float2 f2 = __half22float2(*reinterpret_cast<__half2*>(&zr.z));
        float2 f3 = __half22float2(*reinterpret_cast<__half2*>(&zr.w));
        acc[0] += w * f0.x; acc[1] += w * f0.y;
        acc[2] += w * f1.x; acc[3] += w * f1.y;
        acc[4] += w * f2.x; acc[5] += w * f2.y;
        acc[6] += w * f3.x; acc[7] += w * f3.y;
    }
    for (int s = beg + 64; s < end; ++s) {            // rare tail (deg > 64)
        int sn  = g_esrc[s];
        float e = g_ssrc[sn] + sdn;
        e = (e > 0.f) ? e : LEAKY * e;
        float w = __expf(e) * inv;
        uint4 zr = ((const uint4*)g_zh)[(size_t)sn * 16 + lane];
        float2 f0 = __half22float2(*reinterpret_cast<__half2*>(&zr.x));
        float2 f1 = __half22float2(*reinterpret_cast<__half2*>(&zr.y));
        float2 f2 = __half22float2(*reinterpret_cast<__half2*>(&zr.z));
        float2 f3 = __half22float2(*reinterpret_cast<__half2*>(&zr.w));
        acc[0] += w * f0.x; acc[1] += w * f0.y;
        acc[2] += w * f1.x; acc[3] += w * f1.y;
        acc[4] += w * f2.x; acc[5] += w * f2.y;
        acc[6] += w * f3.x; acc[7] += w * f3.y;
    }
    // ELU (alpha = 1)
#pragma unroll
    for (int j = 0; j < 8; ++j)
        acc[j] = (acc[j] > 0.f) ? acc[j] : (__expf(acc[j]) - 1.f);

    if (ToExt) {
        float4 o0 = make_float4(acc[0], acc[1], acc[2], acc[3]);
        float4 o1 = make_float4(acc[4], acc[5], acc[6], acc[7]);
        ((float4*)out_ext)[(size_t)node * 32 + lane * 2]     = o0;
        ((float4*)out_ext)[(size_t)node * 32 + lane * 2 + 1] = o1;
    } else {      // fp16 h1: direct GEMM2 input
        __half2 p0 = __float22half2_rn(make_float2(acc[0], acc[1]));
        __half2 p1 = __float22half2_rn(make_float2(acc[2], acc[3]));
        __half2 p2 = __float22half2_rn(make_float2(acc[4], acc[5]));
        __half2 p3 = __float22half2_rn(make_float2(acc[6], acc[7]));
        uint4 pk;
        pk.x = *(uint32_t*)&p0; pk.y = *(uint32_t*)&p1;
        pk.z = *(uint32_t*)&p2; pk.w = *(uint32_t*)&p3;
        ((uint4*)g_h1h2)[(size_t)node * 16 + lane] = pk;
    }
}

// ---------------- launch ------------------------------------------------------
extern "C" void kernel_launch(void* const* d_in, const int* in_sizes, int n_in,
                              void* d_out, int out_size) {
    const float* h   = (const float*)d_in[0];
    const int*   src = (const int*)d_in[1];
    const int*   dst = (const int*)d_in[2];
    const float* W1  = (const float*)d_in[3];
    const float* b1  = (const float*)d_in[4];
    const float* a1  = (const float*)d_in[5];
    const float* ab1 = (const float*)d_in[6];
    const float* W2  = (const float*)d_in[7];
    const float* b2  = (const float*)d_in[8];
    const float* a2  = (const float*)d_in[9];
    const float* ab2 = (const float*)d_in[10];
    float* out = (float*)d_out;

    const int NB_E4 = (N_EDGES / 4 + 255) / 256;
    const int NB_W  = (N_NODES + 15) / 16;     // 2 nodes per warp
    const int NB_G  = (N_NODES + 127) / 128;   // 391 tiles
    const int NB_C  = (N_NODES * IN_DIM / 8 + 255) / 256;

    cudaFuncSetAttribute(gemm_mma<IN_DIM, true>,
                         cudaFuncAttributeMaxDynamicSharedMemorySize, GEMM_SMEM);
    cudaFuncSetAttribute(gemm_mma<HID, false>,
                         cudaFuncAttributeMaxDynamicSharedMemorySize, GEMM_SMEM);

    // fork: CSR chain on s2 concurrent with conv + GEMM1 on main stream.
    cudaStream_t s2 = 0;
    cudaEvent_t evFork = nullptr, evCsr = nullptr;
    bool forked =
        cudaStreamCreateWithFlags(&s2, cudaStreamNonBlocking) == cudaSuccess &&
        cudaEventCreateWithFlags(&evFork, cudaEventDisableTiming) == cudaSuccess &&
        cudaEventCreateWithFlags(&evCsr, cudaEventDisableTiming) == cudaSuccess;
    cudaStream_t cs = forked ? s2 : (cudaStream_t)0;
    if (forked) {
        cudaEventRecord(evFork, 0);
        cudaStreamWaitEvent(s2, evFork, 0);
    }

    hist_kernel<<<NB_E4, 256, 0, cs>>>(dst);                          // 1
    conv_kernel<<<NB_C, 256>>>(W1, W2, h);                            // 2
    scanAB_kernel<<<SCAN_BLK, 256, 0, cs>>>();                        // 3
    gemm_mma<IN_DIM, true><<<NB_G, 256, GEMM_SMEM>>>(b1, a1);         // 4 (profiled)
    scanC_kernel<<<SCAN_BLK, 256, 0, cs>>>();                         // 5
    fill_kernel<<<NB_E4, 256, 0, cs>>>(dst, src);                     // 6
    if (forked) cudaEventRecord(evCsr, s2);

    if (forked) cudaStreamWaitEvent(0, evCsr, 0);
    agg_kernel<false><<<NB_W, 256>>>(ab1, nullptr);                   // 7

    gemm_mma<HID, false><<<NB_G, 256, GEMM_SMEM>>>(b2, a2);           // 8
    agg_kernel<true><<<NB_W, 256>>>(ab2, out);                        // 9
    // streams/events intentionally leaked: replays run the captured graph only.
}

// round 17
// speedup vs baseline: 1.0447x; 1.0447x over previous
#include <cuda_runtime.h>
#include <cuda_fp16.h>
#include <cstdint>
#include <limits.h>

#define N_NODES 50000
#define N_EDGES 800000
#define IN_DIM  256
#define HID     128
#define LEAKY   0.01f
#define SCAN_BLK 196                       // ceil(50000 / 256)

// ---------------- scratch (device globals; device-side use ONLY) -------------
// NOTE: relies on CUDA zero-initialization of __device__ globals at module
// load for the FIRST run; scanAB/scanC restore the zero-state for replays.
__device__ __align__(16) __half2 g_zh[N_NODES * 64];        // z fp16 (gather payload)
__device__ __align__(16) __half2 g_hh2[N_NODES * IN_DIM/2]; // input h in fp16
__device__ __align__(16) __half2 g_h1h2[N_NODES * HID/2];   // layer-1 out in fp16
__device__ __align__(16) __half  g_W1h[HID * IN_DIM];       // fp16 W1
__device__ __align__(16) __half  g_W2h[HID * HID];          // fp16 W2
__device__ float g_ssrc[N_NODES];
__device__ float g_sdst[N_NODES];
__device__ int   g_cnt[N_NODES];           // zero at entry of every run
__device__ int   g_off[N_NODES + 1];
__device__ int   g_cur[N_NODES];
__device__ int   g_esrc[N_EDGES];          // CSR (by dst) -> src node id
__device__ int   g_bsum[SCAN_BLK];
__device__ int   g_boff[SCAN_BLK];
__device__ int   g_done;                   // scanAB last-block counter (reset each run)

// ---------------- small helpers ----------------------------------------------
__device__ __forceinline__ uint32_t smem_u32(const void* p) {
    uint32_t a;
    asm("{ .reg .u64 t; cvta.to.shared.u64 t, %1; cvt.u32.u64 %0, t; }" : "=r"(a) : "l"(p));
    return a;
}
__device__ __forceinline__ void cp16z(uint32_t dst, const void* src, bool valid) {
    int sz = valid ? 16 : 0;
    asm volatile("cp.async.cg.shared.global [%0], [%1], 16, %2;"
                 :: "r"(dst), "l"(src), "r"(sz));
}
__device__ __forceinline__ void cp16(uint32_t dst, const void* src) {
    asm volatile("cp.async.cg.shared.global [%0], [%1], 16;" :: "r"(dst), "l"(src));
}
#define CP_COMMIT() asm volatile("cp.async.commit_group;" ::: "memory")
#define CP_WAIT(N)  asm volatile("cp.async.wait_group %0;" :: "n"(N) : "memory")

__device__ __forceinline__ void mma_f16(float* c, const uint32_t* a, const uint32_t* b) {
    asm volatile(
        "mma.sync.aligned.m16n8k16.row.col.f32.f16.f16.f32 "
        "{%0,%1,%2,%3}, {%4,%5,%6,%7}, {%8,%9}, {%0,%1,%2,%3};"
        : "+f"(c[0]), "+f"(c[1]), "+f"(c[2]), "+f"(c[3])
        : "r"(a[0]), "r"(a[1]), "r"(a[2]), "r"(a[3]), "r"(b[0]), "r"(b[1]));
}

// ---------------- CSR build --------------------------------------------------
__global__ void hist_kernel(const int* __restrict__ dst) {
    int i = blockIdx.x * blockDim.x + threadIdx.x;
    if (i * 4 < N_EDGES) {
        int4 d = ((const int4*)dst)[i];
        atomicAdd(&g_cnt[d.x], 1);
        atomicAdd(&g_cnt[d.y], 1);
        atomicAdd(&g_cnt[d.z], 1);
        atomicAdd(&g_cnt[d.w], 1);
    }
}
// scanA + scanB fused: per-block sums; LAST finishing block scans the sums.
__global__ __launch_bounds__(256) void scanAB_kernel() {
    __shared__ int sm[256];
    __shared__ int isLast;
    int t = threadIdx.x, i = blockIdx.x * 256 + t;
    int c = (i < N_NODES) ? g_cnt[i] : 0;
    sm[t] = c;
    __syncthreads();
    for (int o = 128; o > 0; o >>= 1) {
        if (t < o) sm[t] += sm[t + o];
        __syncthreads();
    }
    if (t == 0) {
        g_bsum[blockIdx.x] = sm[0];
        __threadfence();
        int prev = atomicAdd(&g_done, 1);
        isLast = (prev == SCAN_BLK - 1) ? 1 : 0;
    }
    __syncthreads();
    if (isLast) {
        // inline scanB: inclusive scan of 196 block sums -> exclusive g_boff
        int v = (t < SCAN_BLK) ? g_bsum[t] : 0;
        sm[t] = v;
        __syncthreads();
        for (int o = 1; o < 256; o <<= 1) {
            int add = (t >= o) ? sm[t - o] : 0;
            __syncthreads();
            sm[t] += add;
            __syncthreads();
        }
        if (t < SCAN_BLK) g_boff[t] = sm[t] - v;
        if (t == 0) {
            g_off[N_NODES] = N_EDGES;
            g_done = 0;                    // reset for next run (replay-safe)
        }
    }
}
// local scan + offsets; also re-zeroes g_cnt for the next run.
__global__ __launch_bounds__(256) void scanC_kernel() {
    __shared__ int sm[256];
    int t = threadIdx.x, i = blockIdx.x * 256 + t;
    int c = (i < N_NODES) ? g_cnt[i] : 0;
    sm[t] = c;
    __syncthreads();
    for (int o = 1; o < 256; o <<= 1) {
        int add = (t >= o) ? sm[t - o] : 0;
        __syncthreads();
        sm[t] += add;
        __syncthreads();
    }
    if (i < N_NODES) {
        int prefix = g_boff[blockIdx.x] + sm[t] - c;  // exclusive
        g_off[i] = prefix;
        g_cur[i] = prefix;
        g_cnt[i] = 0;                     // restore zero-state for next run
    }
}
__global__ void fill_kernel(const int* __restrict__ dst,
                            const int* __restrict__ src) {
    int i = blockIdx.x * blockDim.x + threadIdx.x;
    if (i * 4 < N_EDGES) {
        int4 d = ((const int4*)dst)[i];
        int4 s = ((const int4*)src)[i];
        int p0 = atomicAdd(&g_cur[d.x], 1);
        int p1 = atomicAdd(&g_cur[d.y], 1);
        int p2 = atomicAdd(&g_cur[d.z], 1);
        int p3 = atomicAdd(&g_cur[d.w], 1);
        g_esrc[p0] = s.x;
        g_esrc[p1] = s.y;
        g_esrc[p2] = s.z;
        g_esrc[p3] = s.w;
    }
}

// ---------------- precision conversions (W + h, fused) -----------------------
__global__ void conv_kernel(const float* __restrict__ W1,
                            const float* __restrict__ W2,
                            const float* __restrict__ h) {
    int i = blockIdx.x * blockDim.x + threadIdx.x;
    if (i < HID * IN_DIM) g_W1h[i] = __float2half_rn(W1[i]);
    if (i < HID * HID)    g_W2h[i] = __float2half_rn(W2[i]);
    if (i * 8 < N_NODES * IN_DIM) {
        float4 v0 = ((const float4*)h)[i * 2];
        float4 v1 = ((const float4*)h)[i * 2 + 1];
        __half2 o0 = __float22half2_rn(make_float2(v0.x, v0.y));
        __half2 o1 = __float22half2_rn(make_float2(v0.z, v0.w));
        __half2 o2 = __float22half2_rn(make_float2(v1.x, v1.y));
        __half2 o3 = __float22half2_rn(make_float2(v1.z, v1.w));
        uint4 pk;
        pk.x = *(uint32_t*)&o0; pk.y = *(uint32_t*)&o1;
        pk.z = *(uint32_t*)&o2; pk.w = *(uint32_t*)&o3;
        ((uint4*)g_hh2)[i] = pk;
    }
}

// ---------------- cp.async double-buffered fp16 GEMM -------------------------
#define STAGE_BYTES 20480
#define GEMM_SMEM   (2 * STAGE_BYTES + 1024)

template <int K, bool L1>
__global__ __launch_bounds__(256) void gemm_mma(
    const float* __restrict__ bias, const float* __restrict__ avec)
{
    const __half* __restrict__ A  = L1 ? (const __half*)g_hh2 : (const __half*)g_h1h2;
    const __half* __restrict__ Wh = L1 ? g_W1h : g_W2h;

    extern __shared__ __align__(16) char dsm[];
    float* sSS = (float*)(dsm + 2 * STAGE_BYTES);
    float* sSD = sSS + 128;
    uint32_t smBase = smem_u32(dsm);

    int tid  = threadIdx.x;
    int wid  = tid >> 5, lane = tid & 31;
    int wr   = wid & 3;
    int wc   = wid >> 2;
    int g4   = lane >> 2;
    int q4   = lane & 3;
    int m0   = blockIdx.x * 128;

    float acc[2][8][4];
#pragma unroll
    for (int mt = 0; mt < 2; ++mt)
#pragma unroll
        for (int nt = 0; nt < 8; ++nt)
#pragma unroll
            for (int j = 0; j < 4; ++j) acc[mt][nt][j] = 0.f;

    const int NT = K / 32;

    auto load_tile = [&](int t, int stage) {
        int k0 = t * 32;
#pragma unroll
        for (int x = tid; x < 1024; x += 256) {
            if (x < 512) {
                int row = x >> 2, q = x & 3;
                int gr = m0 + row;
                uint32_t d = smBase + stage * STAGE_BYTES + row * 80 + q * 16;
                cp16z(d, A + (size_t)gr * K + k0 + q * 8, gr < N_NODES);
            } else {
                int y = x - 512;
                int row = y >> 2, q = y & 3;
                uint32_t d = smBase + stage * STAGE_BYTES + 10240 + row * 80 + q * 16;
                cp16(d, Wh + (size_t)row * K + k0 + q * 8);
            }
        }
        CP_COMMIT();
    };

    load_tile(0, 0);
    for (int t = 0; t < NT; ++t) {
        int cur = t & 1;
        if (t + 1 < NT) { load_tile(t + 1, (t + 1) & 1); CP_WAIT(1); }
        else            { CP_WAIT(0); }
        __syncthreads();

        const uint32_t* Ab = (const uint32_t*)(dsm + cur * STAGE_BYTES);
        const uint32_t* Wb = (const uint32_t*)(dsm + cur * STAGE_BYTES + 10240);
#pragma unroll
        for (int c = 0; c < 2; ++c) {
            int co = c * 8;
            uint32_t afr[2][4];
#pragma unroll
            for (int mt = 0; mt < 2; ++mt) {
                int rb = wr * 32 + mt * 16;
                afr[mt][0] = Ab[(rb + g4) * 20 + co + q4];
                afr[mt][1] = Ab[(rb + 8 + g4) * 20 + co + q4];
                afr[mt][2] = Ab[(rb + g4) * 20 + co + 4 + q4];
                afr[mt][3] = Ab[(rb + 8 + g4) * 20 + co + 4 + q4];
            }
#pragma unroll
            for (int nt = 0; nt < 8; ++nt) {
                int cb = wc * 64 + nt * 8;
                uint32_t bfr[2];
                bfr[0] = Wb[(cb + g4) * 20 + co + q4];
                bfr[1] = Wb[(cb + g4) * 20 + co + 4 + q4];
#pragma unroll
                for (int mt = 0; mt < 2; ++mt)
                    mma_f16(acc[mt][nt], afr[mt], bfr);
            }
        }
        __syncthreads();
    }

    if (tid < 128) { sSS[tid] = 0.f; sSD[tid] = 0.f; }
    __syncthreads();

    // epilogue: + bias, store z (fp16), accumulate attention dots (fp32)
#pragma unroll
    for (int mt = 0; mt < 2; ++mt) {
        float ss0 = 0.f, sd0 = 0.f, ss1 = 0.f, sd1 = 0.f;
        int r0 = m0 + wr * 32 + mt * 16 + g4;
        int r1 = r0 + 8;
#pragma unroll
        for (int nt = 0; nt < 8; ++nt) {
            int cb = wc * 64 + nt * 8 + q4 * 2;
            float bx = __ldg(&bias[cb]), by = __ldg(&bias[cb + 1]);
            float asx = __ldg(&avec[cb]),       asy = __ldg(&avec[cb + 1]);
            float adx = __ldg(&avec[128 + cb]), ady = __ldg(&avec[128 + cb + 1]);
            float v0 = acc[mt][nt][0] + bx, v1 = acc[mt][nt][1] + by;
            float v2 = acc[mt][nt][2] + bx, v3 = acc[mt][nt][3] + by;
            ss0 += v0 * asx + v1 * asy;
            sd0 += v0 * adx + v1 * ady;
            ss1 += v2 * asx + v3 * asy;
            sd1 += v2 * adx + v3 * ady;
            if (r0 < N_NODES)
                g_zh[(size_t)r0 * 64 + (cb >> 1)] = __float22half2_rn(make_float2(v0, v1));
            if (r1 < N_NODES)
                g_zh[(size_t)r1 * 64 + (cb >> 1)] = __float22half2_rn(make_float2(v2, v3));
        }
        int lr0 = wr * 32 + mt * 16 + g4;
        atomicAdd(&sSS[lr0], ss0);
        atomicAdd(&sSD[lr0], sd0);
        atomicAdd(&sSS[lr0 + 8], ss1);
        atomicAdd(&sSD[lr0 + 8], sd1);
    }
    __syncthreads();
    if (tid < 128 && m0 + tid < N_NODES) {
        g_ssrc[m0 + tid] = sSS[tid];
        g_sdst[m0 + tid] = sSD[tid];
    }
}

// ---------------- fused softmax + weighted aggregation + ELU ----------------
// Two nodes per warp (16 lanes each, uint4 row gathers). Single-pass exp+sum
// (no max-subtraction: |e| <= ~5 for this model scale; shift-invariant).
template <bool ToExt>
__global__ __launch_bounds__(256) void agg_kernel(const float* __restrict__ ab_ptr,
                                                  float* __restrict__ out_ext)
{
    __shared__ float sWgt[16][64];
    __shared__ int   sSrc[16][64];
    int gt    = blockIdx.x * blockDim.x + threadIdx.x;
    int node  = gt >> 4;                    // half-warp per node
    int lane  = gt & 15;                    // 0..15
    int hw    = (threadIdx.x >> 4);         // 0..15 half-warp slot in block
    if (node >= N_NODES) return;
    int beg = g_off[node], end = g_off[node + 1], deg = end - beg;
    float sdn = g_sdst[node] + ab_ptr[0];

    float ex[4]; int snv[4];
    float S = 0.f;
#pragma unroll
    for (int l = 0; l < 4; ++l) {
        int s = beg + lane + l * 16;
        float x = 0.f; int sn = 0;
        if (s < end) {
            sn = g_esrc[s];
            float e = g_ssrc[sn] + sdn;
            e = (e > 0.f) ? e : LEAKY * e;
            x = __expf(e);
        }
        ex[l] = x; snv[l] = sn;
        S += x;
    }
    for (int s = beg + 64 + lane; s < end; s += 16) {
        float e = g_ssrc[g_esrc[s]] + sdn;
        e = (e > 0.f) ? e : LEAKY * e;
        S += __expf(e);
    }
#pragma unroll
    for (int o = 8; o > 0; o >>= 1) S += __shfl_xor_sync(0xffffffffu, S, o);
    float inv = (deg > 0) ? (1.f / S) : 0.f;

#pragma unroll
    for (int l = 0; l < 4; ++l) {
        int idx = lane + l * 16;
        if (beg + idx < end) {
            sWgt[hw][idx] = ex[l] * inv;
            sSrc[hw][idx] = snv[l];
        }
    }
    __syncwarp();

    float acc[8] = {0.f, 0.f, 0.f, 0.f, 0.f, 0.f, 0.f, 0.f};
    int nin = deg < 64 ? deg : 64;
#pragma unroll 4
    for (int i = 0; i < nin; ++i) {
        float w  = sWgt[hw][i];
        int   sn = sSrc[hw][i];
        uint4 zr = ((const uint4*)g_zh)[(size_t)sn * 16 + lane];
        float2 f0 = __half22float2(*reinterpret_cast<__half2*>(&zr.x));
        float2 f1 = __half22float2(*reinterpret_cast<__half2*>(&zr.y));
        float2 f2 = __half22float2(*reinterpret_cast<__half2*>(&zr.z));
        float2 f3 = __half22float2(*reinterpret_cast<__half2*>(&zr.w));
        acc[0] += w * f0.x; acc[1] += w * f0.y;
        acc[2] += w * f1.x; acc[3] += w * f1.y;
        acc[4] += w * f2.x; acc[5] += w * f2.y;
        acc[6] += w * f3.x; acc[7] += w * f3.y;
    }
    for (int s = beg + 64; s < end; ++s) {            // rare tail (deg > 64)
        int sn  = g_esrc[s];
        float e = g_ssrc[sn] + sdn;
        e = (e > 0.f) ? e : LEAKY * e;
        float w = __expf(e) * inv;
        uint4 zr = ((const uint4*)g_zh)[(size_t)sn * 16 + lane];
        float2 f0 = __half22float2(*reinterpret_cast<__half2*>(&zr.x));
        float2 f1 = __half22float2(*reinterpret_cast<__half2*>(&zr.y));
        float2 f2 = __half22float2(*reinterpret_cast<__half2*>(&zr.z));
        float2 f3 = __half22float2(*reinterpret_cast<__half2*>(&zr.w));
        acc[0] += w * f0.x; acc[1] += w * f0.y;
        acc[2] += w * f1.x; acc[3] += w * f1.y;
        acc[4] += w * f2.x; acc[5] += w * f2.y;
        acc[6] += w * f3.x; acc[7] += w * f3.y;
    }
    // ELU (alpha = 1)
#pragma unroll
    for (int j = 0; j < 8; ++j)
        acc[j] = (acc[j] > 0.f) ? acc[j] : (__expf(acc[j]) - 1.f);

    if (ToExt) {
        float4 o0 = make_float4(acc[0], acc[1], acc[2], acc[3]);
        float4 o1 = make_float4(acc[4], acc[5], acc[6], acc[7]);
        ((float4*)out_ext)[(size_t)node * 32 + lane * 2]     = o0;
        ((float4*)out_ext)[(size_t)node * 32 + lane * 2 + 1] = o1;
    } else {      // fp16 h1: direct GEMM2 input
        __half2 p0 = __float22half2_rn(make_float2(acc[0], acc[1]));
        __half2 p1 = __float22half2_rn(make_float2(acc[2], acc[3]));
        __half2 p2 = __float22half2_rn(make_float2(acc[4], acc[5]));
        __half2 p3 = __float22half2_rn(make_float2(acc[6], acc[7]));
        uint4 pk;
        pk.x = *(uint32_t*)&p0; pk.y = *(uint32_t*)&p1;
        pk.z = *(uint32_t*)&p2; pk.w = *(uint32_t*)&p3;
        ((uint4*)g_h1h2)[(size_t)node * 16 + lane] = pk;
    }
}

// ---------------- launch ------------------------------------------------------
extern "C" void kernel_launch(void* const* d_in, const int* in_sizes, int n_in,
                              void* d_out, int out_size) {
    const float* h   = (const float*)d_in[0];
    const int*   src = (const int*)d_in[1];
    const int*   dst = (const int*)d_in[2];
    const float* W1  = (const float*)d_in[3];
    const float* b1  = (const float*)d_in[4];
    const float* a1  = (const float*)d_in[5];
    const float* ab1 = (const float*)d_in[6];
    const float* W2  = (const float*)d_in[7];
    const float* b2  = (const float*)d_in[8];
    const float* a2  = (const float*)d_in[9];
    const float* ab2 = (const float*)d_in[10];
    float* out = (float*)d_out;

    const int NB_E4 = (N_EDGES / 4 + 255) / 256;
    const int NB_W  = (N_NODES + 15) / 16;     // 2 nodes per warp
    const int NB_G  = (N_NODES + 127) / 128;   // 391 tiles
    const int NB_C  = (N_NODES * IN_DIM / 8 + 255) / 256;

    cudaFuncSetAttribute(gemm_mma<IN_DIM, true>,
                         cudaFuncAttributeMaxDynamicSharedMemorySize, GEMM_SMEM);
    cudaFuncSetAttribute(gemm_mma<HID, false>,
                         cudaFuncAttributeMaxDynamicSharedMemorySize, GEMM_SMEM);

    // fork: CSR chain on s2 concurrent with conv + GEMM1 on main stream.
    cudaStream_t s2 = 0;
    cudaEvent_t evFork = nullptr, evCsr = nullptr;
    bool forked =
        cudaStreamCreateWithFlags(&s2, cudaStreamNonBlocking) == cudaSuccess &&
        cudaEventCreateWithFlags(&evFork, cudaEventDisableTiming) == cudaSuccess &&
        cudaEventCreateWithFlags(&evCsr, cudaEventDisableTiming) == cudaSuccess;
    cudaStream_t cs = forked ? s2 : (cudaStream_t)0;
    if (forked) {
        cudaEventRecord(evFork, 0);
        cudaStreamWaitEvent(s2, evFork, 0);
    }

    hist_kernel<<<NB_E4, 256, 0, cs>>>(dst);                          // 1
    conv_kernel<<<NB_C, 256>>>(W1, W2, h);                            // 2
    scanAB_kernel<<<SCAN_BLK, 256, 0, cs>>>();                        // 3
    gemm_mma<IN_DIM, true><<<NB_G, 256, GEMM_SMEM>>>(b1, a1);         // 4
    scanC_kernel<<<SCAN_BLK, 256, 0, cs>>>();                         // 5
    fill_kernel<<<NB_E4, 256, 0, cs>>>(dst, src);                     // 6
    if (forked) cudaEventRecord(evCsr, s2);

    if (forked) cudaStreamWaitEvent(0, evCsr, 0);
    agg_kernel<false><<<NB_W, 256>>>(ab1, nullptr);                   // 7

    gemm_mma<HID, false><<<NB_G, 256, GEMM_SMEM>>>(b2, a2);           // 8
    agg_kernel<true><<<NB_W, 256>>>(ab2, out);                        // 9
    // streams/events intentionally leaked: replays run the captured graph only.
}